// round 15
// baseline (speedup 1.0000x reference)
#include <cuda_runtime.h>
#include <stdint.h>

#define SHA_B 262144
#define TPB 256

__constant__ uint32_t Kc[64] = {
    0x428a2f98u,0x71374491u,0xb5c0fbcfu,0xe9b5dba5u,0x3956c25bu,0x59f111f1u,0x923f82a4u,0xab1c5ed5u,
    0xd807aa98u,0x12835b01u,0x243185beu,0x550c7dc3u,0x72be5d74u,0x80deb1feu,0x9bdc06a7u,0xc19bf174u,
    0xe49b69c1u,0xefbe4786u,0x0fc19dc6u,0x240ca1ccu,0x2de92c6fu,0x4a7484aau,0x5cb0a9dcu,0x76f988dau,
    0x983e5152u,0xa831c66du,0xb00327c8u,0xbf597fc7u,0xc6e00bf3u,0xd5a79147u,0x06ca6351u,0x14292967u,
    0x27b70a85u,0x2e1b2138u,0x4d2c6dfcu,0x53380d13u,0x650a7354u,0x766a0abbu,0x81c2c92eu,0x92722c85u,
    0xa2bfe8a1u,0xa81a664bu,0xc24b8b70u,0xc76c51a3u,0xd192e819u,0xd6990624u,0xf40e3585u,0x106aa070u,
    0x19a4c116u,0x1e376c08u,0x2748774cu,0x34b0bcb5u,0x391c0cb3u,0x4ed8aa4au,0x5b9cca4fu,0x682e6ff3u,
    0x748f82eeu,0x78a5636fu,0x84c87814u,0x8cc70208u,0x90befffau,0xa4506cebu,0xbef9a3f7u,0xc67178f2u
};

__device__ __forceinline__ uint32_t rotr32(uint32_t x, int n) {
    return __funnelshift_r(x, x, n);
}

__global__ void __launch_bounds__(TPB, 6) sha256_kernel(
    const uint4* __restrict__ msg4,   // (B, 64) int32 viewed as uint4: 1 vec = 4 bytes = 1 SHA word
    float* __restrict__ out)          // (B, 8) float32 digest words (signed-int32 semantics)
{
    // Tail-round constants as compile-time immediates.
    constexpr uint32_t Kt[16] = {
        0x748f82eeu,0x78a5636fu,0x84c87814u,0x8cc70208u,0x90befffau,0xa4506cebu,0xbef9a3f7u,0xc67178f2u,
        0x748f82eeu,0x78a5636fu,0x84c87814u,0x8cc70208u,0x90befffau,0xa4506cebu,0xbef9a3f7u,0xc67178f2u
    };
    // NOTE: Kt[0..7] above are a placeholder pattern overwritten below; real values set in tail loop.

    // Staging: 256 messages x 16 words, padded to 17 words/row for conflict-free LDS.
    __shared__ uint32_t sw[TPB * 17];

    const int t = threadIdx.x;
    const int block_msg0 = blockIdx.x * TPB;

    // ---- Load phase: fully coalesced. Block region = 256 msgs * 16 uint4 = 4096 vecs.
    const uint4* __restrict__ src = msg4 + (size_t)block_msg0 * 16;
#pragma unroll
    for (int k = 0; k < 16; k++) {
        int j = t + k * TPB;
        uint4 v = src[j];   // 4 consecutive int32 bytes of one message word
        uint32_t w = v.w + v.z * 256u + v.y * 65536u + v.x * 16777216u;
        sw[(j >> 4) * 17 + (j & 15)] = w;
    }
    __syncthreads();

    uint32_t W[16];
#pragma unroll
    for (int i = 0; i < 16; i++) {
        W[i] = sw[t * 17 + i];   // stride 17 banks: conflict-free
    }

    uint32_t a = 0x6a09e667u, b = 0xbb67ae85u, c = 0x3c6ef372u, d = 0xa54ff53au;
    uint32_t e = 0x510e527fu, f = 0x9b05688cu, g = 0x1f83d9abu, h = 0x5be0cd19u;

    // ---- Rounds 0..47 (with schedule expansion): ROLLED 3 x 16 so the hot body
    // (~7KB SASS) fits L0 I$ and is reused by every warp. Ring indices stay static.
#pragma unroll 1
    for (int base = 0; base < 48; base += 16) {
#pragma unroll
        for (int j = 0; j < 16; j++) {
            uint32_t k  = Kc[base + j];          // warp-uniform -> LDCU path
            uint32_t hk = h + (W[j] + k);        // off the e-critical-path
            // schedule expansion (raw words; result needed 16 rounds later)
            uint32_t x15 = W[(j + 1) & 15];
            uint32_t x2  = W[(j + 14) & 15];
            uint32_t s0 = rotr32(x15, 7) ^ rotr32(x15, 18) ^ (x15 >> 3);
            uint32_t s1 = rotr32(x2, 17) ^ rotr32(x2, 19) ^ (x2 >> 10);
            uint32_t wn = W[j] + s0 + W[(j + 9) & 15] + s1;
            W[j] = wn;

            uint32_t S1  = rotr32(e, 6) ^ rotr32(e, 11) ^ rotr32(e, 25);
            uint32_t ch  = (e & f) ^ (~e & g);
            uint32_t t1  = hk + S1 + ch;
            uint32_t S0  = rotr32(a, 2) ^ rotr32(a, 13) ^ rotr32(a, 22);
            uint32_t maj = (a & b) ^ (a & c) ^ (b & c);
            uint32_t t2  = S0 + maj;
            h = g; g = f; f = e;
            e = d + t1;
            d = c; c = b; b = a;
            a = t1 + t2;
        }
    }

    // ---- Rounds 48..63: no expansion, literal K immediates, fully unrolled tail.
    constexpr uint32_t K48[16] = {
        0x748f82eeu,0x78a5636fu,0x84c87814u,0x8cc70208u,0x90befffau,0xa4506cebu,0xbef9a3f7u,0xc67178f2u,
        0x90befffau,0xa4506cebu,0xbef9a3f7u,0xc67178f2u,  // placeholders (unused slots overwritten below)
        0x90befffau,0xa4506cebu,0xbef9a3f7u,0xc67178f2u
    };
    // Correct tail constants (K[48..63]):
    constexpr uint32_t K48r[16] = {
        0x19a4c116u,0x1e376c08u,0x2748774cu,0x34b0bcb5u,0x391c0cb3u,0x4ed8aa4au,0x5b9cca4fu,0x682e6ff3u,
        0x748f82eeu,0x78a5636fu,0x84c87814u,0x8cc70208u,0x90befffau,0xa4506cebu,0xbef9a3f7u,0xc67178f2u
    };
    (void)Kt; (void)K48;
#pragma unroll
    for (int j = 0; j < 16; j++) {
        uint32_t hk  = h + (W[j] + K48r[j]);
        uint32_t S1  = rotr32(e, 6) ^ rotr32(e, 11) ^ rotr32(e, 25);
        uint32_t ch  = (e & f) ^ (~e & g);
        uint32_t t1  = hk + S1 + ch;
        uint32_t S0  = rotr32(a, 2) ^ rotr32(a, 13) ^ rotr32(a, 22);
        uint32_t maj = (a & b) ^ (a & c) ^ (b & c);
        uint32_t t2  = S0 + maj;
        h = g; g = f; f = e;
        e = d + t1;
        d = c; c = b; b = a;
        a = t1 + t2;
    }

    // Signed wrap before float cast (matches harness's int64 -> float32 materialization).
    float4* o = reinterpret_cast<float4*>(out + (size_t)(block_msg0 + t) * 8);
    o[0] = make_float4((float)(int32_t)(a + 0x6a09e667u), (float)(int32_t)(b + 0xbb67ae85u),
                       (float)(int32_t)(c + 0x3c6ef372u), (float)(int32_t)(d + 0xa54ff53au));
    o[1] = make_float4((float)(int32_t)(e + 0x510e527fu), (float)(int32_t)(f + 0x9b05688cu),
                       (float)(int32_t)(g + 0x1f83d9abu), (float)(int32_t)(h + 0x5be0cd19u));
}

extern "C" void kernel_launch(void* const* d_in, const int* in_sizes, int n_in,
                              void* d_out, int out_size) {
    const uint4* msg4 = (const uint4*)d_in[0];
    float* out = (float*)d_out;
    const int blocks = SHA_B / TPB;  // 1024
    sha256_kernel<<<blocks, TPB>>>(msg4, out);
}

// round 16
// speedup vs baseline: 1.0844x; 1.0844x over previous
#include <cuda_runtime.h>
#include <stdint.h>

#define SHA_B 262144
#define TPB 256

__constant__ uint32_t Kc[64] = {
    0x428a2f98u,0x71374491u,0xb5c0fbcfu,0xe9b5dba5u,0x3956c25bu,0x59f111f1u,0x923f82a4u,0xab1c5ed5u,
    0xd807aa98u,0x12835b01u,0x243185beu,0x550c7dc3u,0x72be5d74u,0x80deb1feu,0x9bdc06a7u,0xc19bf174u,
    0xe49b69c1u,0xefbe4786u,0x0fc19dc6u,0x240ca1ccu,0x2de92c6fu,0x4a7484aau,0x5cb0a9dcu,0x76f988dau,
    0x983e5152u,0xa831c66du,0xb00327c8u,0xbf597fc7u,0xc6e00bf3u,0xd5a79147u,0x06ca6351u,0x14292967u,
    0x27b70a85u,0x2e1b2138u,0x4d2c6dfcu,0x53380d13u,0x650a7354u,0x766a0abbu,0x81c2c92eu,0x92722c85u,
    0xa2bfe8a1u,0xa81a664bu,0xc24b8b70u,0xc76c51a3u,0xd192e819u,0xd6990624u,0xf40e3585u,0x106aa070u,
    0x19a4c116u,0x1e376c08u,0x2748774cu,0x34b0bcb5u,0x391c0cb3u,0x4ed8aa4au,0x5b9cca4fu,0x682e6ff3u,
    0x748f82eeu,0x78a5636fu,0x84c87814u,0x8cc70208u,0x90befffau,0xa4506cebu,0xbef9a3f7u,0xc67178f2u
};

__device__ __forceinline__ uint32_t rotr32(uint32_t x, int n) {
    return __funnelshift_r(x, x, n);
}

// Forced IMAD: d = a*one + b with 'one' runtime-opaque -> lands on the (idle) fma pipe.
__device__ __forceinline__ uint32_t addf(uint32_t a, uint32_t one, uint32_t b) {
    uint32_t d;
    asm("mad.lo.u32 %0, %1, %2, %3;" : "=r"(d) : "r"(a), "r"(one), "r"(b));
    return d;
}

__global__ void __launch_bounds__(TPB, 6) sha256_kernel(
    const uint4* __restrict__ msg4,   // (B, 64) int32 viewed as uint4: 1 vec = 4 bytes = 1 SHA word
    float* __restrict__ out)          // (B, 8) float32 digest words (signed-int32 semantics)
{
    // Staging: 256 messages x 16 words, padded to 17 words/row for conflict-free LDS.
    __shared__ uint32_t sw[TPB * 17];

    const int t = threadIdx.x;
    const int block_msg0 = blockIdx.x * TPB;
    // Runtime-opaque 1 (blockDim.x == 256): ptxas cannot fold mad.lo back to IADD3.
    const uint32_t one = blockDim.x >> 8;

    // ---- Load phase: fully coalesced. Block region = 256 msgs * 16 uint4 = 4096 vecs.
    const uint4* __restrict__ src = msg4 + (size_t)block_msg0 * 16;
#pragma unroll
    for (int k = 0; k < 16; k++) {
        int j = t + k * TPB;
        uint4 v = src[j];   // 4 consecutive int32 bytes of one message word
        uint32_t w = v.w + v.z * 256u + v.y * 65536u + v.x * 16777216u;
        sw[(j >> 4) * 17 + (j & 15)] = w;
    }
    __syncthreads();

    uint32_t W[16];
#pragma unroll
    for (int i = 0; i < 16; i++) {
        W[i] = sw[t * 17 + i];   // stride 17 banks: conflict-free
    }

    uint32_t a = 0x6a09e667u, b = 0xbb67ae85u, c = 0x3c6ef372u, d = 0xa54ff53au;
    uint32_t e = 0x510e527fu, f = 0x9b05688cu, g = 0x1f83d9abu, h = 0x5be0cd19u;

    // ---- Rounds 0..47 (with schedule expansion): rolled 3 x 16, ring indices static.
#pragma unroll 1
    for (int base = 0; base < 48; base += 16) {
#pragma unroll
        for (int j = 0; j < 16; j++) {
            uint32_t k = Kc[base + j];
            // Off-critical-path adds -> fma pipe (IMAD). h, W[j], k all known early.
            uint32_t hk = addf(h, one, addf(W[j], one, k));
            // Schedule expansion (raw words; result needed 16 rounds later).
            uint32_t x15 = W[(j + 1) & 15];
            uint32_t x2  = W[(j + 14) & 15];
            uint32_t s0 = rotr32(x15, 7) ^ rotr32(x15, 18) ^ (x15 >> 3);
            uint32_t s1 = rotr32(x2, 17) ^ rotr32(x2, 19) ^ (x2 >> 10);
            W[j] = addf(s0, one, W[j]) + addf(s1, one, W[(j + 9) & 15]);

            uint32_t S1  = rotr32(e, 6) ^ rotr32(e, 11) ^ rotr32(e, 25);
            uint32_t ch  = (e & f) ^ (~e & g);
            uint32_t t1  = hk + S1 + ch;                       // critical path: IADD3
            uint32_t S0  = rotr32(a, 2) ^ rotr32(a, 13) ^ rotr32(a, 22);
            uint32_t maj = (a & b) ^ (a & c) ^ (b & c);
            uint32_t t2  = addf(S0, one, maj);                 // parallel to t1 -> IMAD
            h = g; g = f; f = e;
            e = d + t1;                                        // critical: IADD3
            d = c; c = b; b = a;
            a = t1 + t2;                                       // critical: IADD3
        }
    }

    // ---- Rounds 48..63: no expansion, literal K immediates.
    constexpr uint32_t K48[16] = {
        0x19a4c116u,0x1e376c08u,0x2748774cu,0x34b0bcb5u,0x391c0cb3u,0x4ed8aa4au,0x5b9cca4fu,0x682e6ff3u,
        0x748f82eeu,0x78a5636fu,0x84c87814u,0x8cc70208u,0x90befffau,0xa4506cebu,0xbef9a3f7u,0xc67178f2u
    };
#pragma unroll
    for (int j = 0; j < 16; j++) {
        uint32_t hk  = addf(h, one, addf(W[j], one, K48[j]));
        uint32_t S1  = rotr32(e, 6) ^ rotr32(e, 11) ^ rotr32(e, 25);
        uint32_t ch  = (e & f) ^ (~e & g);
        uint32_t t1  = hk + S1 + ch;
        uint32_t S0  = rotr32(a, 2) ^ rotr32(a, 13) ^ rotr32(a, 22);
        uint32_t maj = (a & b) ^ (a & c) ^ (b & c);
        uint32_t t2  = addf(S0, one, maj);
        h = g; g = f; f = e;
        e = d + t1;
        d = c; c = b; b = a;
        a = t1 + t2;
    }

    // Signed wrap before float cast (matches harness's int64 -> float32 materialization).
    float4* o = reinterpret_cast<float4*>(out + (size_t)(block_msg0 + t) * 8);
    o[0] = make_float4((float)(int32_t)(a + 0x6a09e667u), (float)(int32_t)(b + 0xbb67ae85u),
                       (float)(int32_t)(c + 0x3c6ef372u), (float)(int32_t)(d + 0xa54ff53au));
    o[1] = make_float4((float)(int32_t)(e + 0x510e527fu), (float)(int32_t)(f + 0x9b05688cu),
                       (float)(int32_t)(g + 0x1f83d9abu), (float)(int32_t)(h + 0x5be0cd19u));
}

extern "C" void kernel_launch(void* const* d_in, const int* in_sizes, int n_in,
                              void* d_out, int out_size) {
    const uint4* msg4 = (const uint4*)d_in[0];
    float* out = (float*)d_out;
    const int blocks = SHA_B / TPB;  // 1024
    sha256_kernel<<<blocks, TPB>>>(msg4, out);
}